// round 1
// baseline (speedup 1.0000x reference)
#include <cuda_runtime.h>
#include <cuda_bf16.h>

#define BQ   64
#define SEQ  341
#define DIM  768
#define NH   12
#define HD   64
#define MROWS (BQ * SEQ)      // 21824
#define QKV_COLS (3 * DIM)    // 2304

// Scratch (no device allocation allowed): q/k/v in [B,H,N,hd], attn out in [B,N,D]
__device__ float g_q[(size_t)BQ * NH * SEQ * HD];
__device__ float g_k[(size_t)BQ * NH * SEQ * HD];
__device__ float g_v[(size_t)BQ * NH * SEQ * HD];
__device__ float g_ao[(size_t)MROWS * DIM];

// ---------------------------------------------------------------------------
// SGEMM core: C[m,n] = sum_k A[m,K] * W[n,K]   (A row-major [M,K], W row-major [Ncols,K])
// 128x128 tile, BK=8, 256 threads, 8x8 per-thread micro-tile.
// ---------------------------------------------------------------------------

__global__ __launch_bounds__(256) void qkv_kernel(
    const float* __restrict__ x,      // [MROWS, DIM]
    const float* __restrict__ w,      // [QKV_COLS, DIM]
    const float* __restrict__ bias)   // [QKV_COLS]
{
    __shared__ float As[8][128];
    __shared__ float Bs[8][128];

    const int K = DIM;
    const int tid = threadIdx.x;
    const int blockRow = blockIdx.x;
    const int blockCol = blockIdx.y;

    const int loadRow = tid >> 1;        // 0..127
    const int loadCol = (tid & 1) * 4;   // 0 or 4
    const int threadRow = tid >> 4;      // 0..15
    const int threadCol = tid & 15;      // 0..15

    float acc[8][8];
    #pragma unroll
    for (int i = 0; i < 8; i++)
        #pragma unroll
        for (int j = 0; j < 8; j++) acc[i][j] = 0.f;

    const int aRow = blockRow * 128 + loadRow;
    const bool aValid = (aRow < MROWS);
    const int bRow = blockCol * 128 + loadRow;

    for (int k0 = 0; k0 < K; k0 += 8) {
        float4 av = aValid
            ? *reinterpret_cast<const float4*>(x + (size_t)aRow * K + k0 + loadCol)
            : make_float4(0.f, 0.f, 0.f, 0.f);
        float4 bv = *reinterpret_cast<const float4*>(w + (size_t)bRow * K + k0 + loadCol);

        As[loadCol + 0][loadRow] = av.x;
        As[loadCol + 1][loadRow] = av.y;
        As[loadCol + 2][loadRow] = av.z;
        As[loadCol + 3][loadRow] = av.w;
        Bs[loadCol + 0][loadRow] = bv.x;
        Bs[loadCol + 1][loadRow] = bv.y;
        Bs[loadCol + 2][loadRow] = bv.z;
        Bs[loadCol + 3][loadRow] = bv.w;
        __syncthreads();

        #pragma unroll
        for (int kk = 0; kk < 8; kk++) {
            float rm[8], rn[8];
            float4 t0 = *reinterpret_cast<const float4*>(&As[kk][threadRow * 8]);
            float4 t1 = *reinterpret_cast<const float4*>(&As[kk][threadRow * 8 + 4]);
            rm[0]=t0.x; rm[1]=t0.y; rm[2]=t0.z; rm[3]=t0.w;
            rm[4]=t1.x; rm[5]=t1.y; rm[6]=t1.z; rm[7]=t1.w;
            float4 u0 = *reinterpret_cast<const float4*>(&Bs[kk][threadCol * 8]);
            float4 u1 = *reinterpret_cast<const float4*>(&Bs[kk][threadCol * 8 + 4]);
            rn[0]=u0.x; rn[1]=u0.y; rn[2]=u0.z; rn[3]=u0.w;
            rn[4]=u1.x; rn[5]=u1.y; rn[6]=u1.z; rn[7]=u1.w;
            #pragma unroll
            for (int i = 0; i < 8; i++)
                #pragma unroll
                for (int j = 0; j < 8; j++)
                    acc[i][j] = fmaf(rm[i], rn[j], acc[i][j]);
        }
        __syncthreads();
    }

    // Epilogue: bias add, scatter into q/k/v [B,H,N,hd]
    #pragma unroll
    for (int i = 0; i < 8; i++) {
        int m = blockRow * 128 + threadRow * 8 + i;
        if (m >= MROWS) continue;
        int b = m / SEQ;
        int n = m - b * SEQ;
        #pragma unroll
        for (int j = 0; j < 8; j++) {
            int e = blockCol * 128 + threadCol * 8 + j;
            float val = acc[i][j] + __ldg(&bias[e]);
            int which = e / DIM;         // 0=q,1=k,2=v
            int d = e - which * DIM;
            int h = d >> 6;
            int hh = d & 63;
            float* dst = (which == 0) ? g_q : (which == 1) ? g_k : g_v;
            dst[(((size_t)b * NH + h) * SEQ + n) * HD + hh] = val;
        }
    }
}

__global__ __launch_bounds__(256) void proj_kernel(
    const float* __restrict__ w,      // [DIM, DIM]
    const float* __restrict__ bias,   // [DIM]
    float* __restrict__ out)          // [MROWS, DIM]
{
    __shared__ float As[8][128];
    __shared__ float Bs[8][128];

    const int K = DIM;
    const int tid = threadIdx.x;
    const int blockRow = blockIdx.x;
    const int blockCol = blockIdx.y;

    const int loadRow = tid >> 1;
    const int loadCol = (tid & 1) * 4;
    const int threadRow = tid >> 4;
    const int threadCol = tid & 15;

    float acc[8][8];
    #pragma unroll
    for (int i = 0; i < 8; i++)
        #pragma unroll
        for (int j = 0; j < 8; j++) acc[i][j] = 0.f;

    const int aRow = blockRow * 128 + loadRow;
    const bool aValid = (aRow < MROWS);
    const int bRow = blockCol * 128 + loadRow;

    for (int k0 = 0; k0 < K; k0 += 8) {
        float4 av = aValid
            ? *reinterpret_cast<const float4*>(g_ao + (size_t)aRow * K + k0 + loadCol)
            : make_float4(0.f, 0.f, 0.f, 0.f);
        float4 bv = *reinterpret_cast<const float4*>(w + (size_t)bRow * K + k0 + loadCol);

        As[loadCol + 0][loadRow] = av.x;
        As[loadCol + 1][loadRow] = av.y;
        As[loadCol + 2][loadRow] = av.z;
        As[loadCol + 3][loadRow] = av.w;
        Bs[loadCol + 0][loadRow] = bv.x;
        Bs[loadCol + 1][loadRow] = bv.y;
        Bs[loadCol + 2][loadRow] = bv.z;
        Bs[loadCol + 3][loadRow] = bv.w;
        __syncthreads();

        #pragma unroll
        for (int kk = 0; kk < 8; kk++) {
            float rm[8], rn[8];
            float4 t0 = *reinterpret_cast<const float4*>(&As[kk][threadRow * 8]);
            float4 t1 = *reinterpret_cast<const float4*>(&As[kk][threadRow * 8 + 4]);
            rm[0]=t0.x; rm[1]=t0.y; rm[2]=t0.z; rm[3]=t0.w;
            rm[4]=t1.x; rm[5]=t1.y; rm[6]=t1.z; rm[7]=t1.w;
            float4 u0 = *reinterpret_cast<const float4*>(&Bs[kk][threadCol * 8]);
            float4 u1 = *reinterpret_cast<const float4*>(&Bs[kk][threadCol * 8 + 4]);
            rn[0]=u0.x; rn[1]=u0.y; rn[2]=u0.z; rn[3]=u0.w;
            rn[4]=u1.x; rn[5]=u1.y; rn[6]=u1.z; rn[7]=u1.w;
            #pragma unroll
            for (int i = 0; i < 8; i++)
                #pragma unroll
                for (int j = 0; j < 8; j++)
                    acc[i][j] = fmaf(rm[i], rn[j], acc[i][j]);
        }
        __syncthreads();
    }

    #pragma unroll
    for (int i = 0; i < 8; i++) {
        int m = blockRow * 128 + threadRow * 8 + i;
        if (m >= MROWS) continue;
        #pragma unroll
        for (int j = 0; j < 8; j++) {
            int e = blockCol * 128 + threadCol * 8 + j;
            out[(size_t)m * DIM + e] = acc[i][j] + __ldg(&bias[e]);
        }
    }
}

// ---------------------------------------------------------------------------
// Attention: one block per (b,h). Full K,V staged in shared memory (174.6 KB).
// One thread per query row, online softmax over the allowed key prefix.
// Mask is scale-causal: allowed keys form prefix [0, kmax(row)), except CLS
// (row 0) which attends to everything.
// ---------------------------------------------------------------------------

__device__ __forceinline__ int kmax_for_row(int r) {
    if (r == 0)  return SEQ;   // CLS attends everywhere
    if (r < 5)   return 5;     // scale 1 (cum: 1,5,21,85,341)
    if (r < 21)  return 21;    // scale 2
    if (r < 85)  return 85;    // scale 3
    return SEQ;                // scale 4
}

__global__ __launch_bounds__(256) void attn_kernel() {
    extern __shared__ float sh[];
    float* Ks = sh;                 // [SEQ][HD]
    float* Vs = sh + SEQ * HD;      // [SEQ][HD]

    const int bh = blockIdx.x;          // b*NH + h
    const size_t base = (size_t)bh * SEQ * HD;
    const int tid = threadIdx.x;

    // Stage K and V (float4)
    {
        const float4* k4 = reinterpret_cast<const float4*>(g_k + base);
        const float4* v4 = reinterpret_cast<const float4*>(g_v + base);
        float4* ks4 = reinterpret_cast<float4*>(Ks);
        float4* vs4 = reinterpret_cast<float4*>(Vs);
        for (int i = tid; i < SEQ * HD / 4; i += 256) {
            ks4[i] = k4[i];
            vs4[i] = v4[i];
        }
    }
    __syncthreads();

    const int b = bh / NH;
    const int h = bh - b * NH;

    for (int row = tid; row < SEQ; row += 256) {
        float q[HD];
        {
            const float4* q4 = reinterpret_cast<const float4*>(g_q + base + (size_t)row * HD);
            #pragma unroll
            for (int i = 0; i < 16; i++) {
                float4 t = q4[i];
                q[4*i+0] = t.x; q[4*i+1] = t.y; q[4*i+2] = t.z; q[4*i+3] = t.w;
            }
        }

        const int kmax = kmax_for_row(row);
        float mx = -1e30f, l = 0.f;
        float acc[HD];
        #pragma unroll
        for (int d = 0; d < HD; d++) acc[d] = 0.f;

        for (int j = 0; j < kmax; j++) {
            const float* kp = Ks + j * HD;
            float s0 = 0.f, s1 = 0.f, s2 = 0.f, s3 = 0.f;
            #pragma unroll
            for (int d = 0; d < HD; d += 4) {
                s0 = fmaf(q[d+0], kp[d+0], s0);
                s1 = fmaf(q[d+1], kp[d+1], s1);
                s2 = fmaf(q[d+2], kp[d+2], s2);
                s3 = fmaf(q[d+3], kp[d+3], s3);
            }
            float s = ((s0 + s1) + (s2 + s3)) * 0.125f;

            const float* vp = Vs + j * HD;
            if (s <= mx) {
                // common path: running max unchanged
                float p = __expf(s - mx);
                l += p;
                #pragma unroll
                for (int d = 0; d < HD; d++)
                    acc[d] = fmaf(p, vp[d], acc[d]);
            } else {
                float c = __expf(mx - s);   // first iter: exp(-huge) = 0
                mx = s;
                l = fmaf(l, c, 1.f);
                #pragma unroll
                for (int d = 0; d < HD; d++)
                    acc[d] = fmaf(acc[d], c, vp[d]);
            }
        }

        const float inv = 1.f / l;
        float* op = g_ao + ((size_t)(b * SEQ + row)) * DIM + h * HD;
        #pragma unroll
        for (int d = 0; d < HD; d++)
            op[d] = acc[d] * inv;
    }
}

// ---------------------------------------------------------------------------
// Launch
// ---------------------------------------------------------------------------

extern "C" void kernel_launch(void* const* d_in, const int* in_sizes, int n_in,
                              void* d_out, int out_size) {
    const float* x      = (const float*)d_in[0];  // [64,341,768]
    const float* qkv_w  = (const float*)d_in[1];  // [2304,768]
    const float* qkv_b  = (const float*)d_in[2];  // [2304]
    const float* proj_w = (const float*)d_in[3];  // [768,768]
    const float* proj_b = (const float*)d_in[4];  // [768]
    float* out = (float*)d_out;                   // [64,341,768]

    const int smem_attn = 2 * SEQ * HD * (int)sizeof(float);  // 174592 B
    cudaFuncSetAttribute(attn_kernel, cudaFuncAttributeMaxDynamicSharedMemorySize, smem_attn);

    dim3 gQkv((MROWS + 127) / 128, QKV_COLS / 128);   // 171 x 18
    qkv_kernel<<<gQkv, 256>>>(x, qkv_w, qkv_b);

    attn_kernel<<<BQ * NH, 256, smem_attn>>>();       // 768 blocks

    dim3 gProj((MROWS + 127) / 128, DIM / 128);       // 171 x 6
    proj_kernel<<<gProj, 256>>>(proj_w, proj_b, out);
}

// round 5
// speedup vs baseline: 1.8796x; 1.8796x over previous
#include <cuda_runtime.h>
#include <cuda_bf16.h>
#include <cstdint>

#define BQ   64
#define SEQ  341
#define DIM  768
#define NH   12
#define HD   64
#define MROWS (BQ * SEQ)      // 21824
#define QKV_COLS (3 * DIM)    // 2304

// Scratch (no device allocation allowed)
__device__ float g_q[(size_t)BQ * NH * SEQ * HD];
__device__ float g_k[(size_t)BQ * NH * SEQ * HD];
__device__ float g_v[(size_t)BQ * NH * SEQ * HD];
__device__ float g_ao[(size_t)MROWS * DIM];

// ---------------------------------------------------------------------------
// TF32 tensor-core GEMM: C[m,n] = sum_k A[m,k] * W[n,k]
// BM=128, BN=128, BK=32, 256 threads = 8 warps in 4x2 (warp tile 32x64).
// mma.sync.aligned.m16n8k8.row.col.f32.tf32.tf32.f32
// ---------------------------------------------------------------------------

#define SMSTRIDE 36   // 32 + 4 pad (keeps float4 stores 16B aligned, kills conflicts)

__device__ __forceinline__ uint32_t to_tf32(float x) {
    uint32_t y;
    asm("cvt.rna.tf32.f32 %0, %1;" : "=r"(y) : "f"(x));
    return y;
}

__device__ __forceinline__ void mma_tf32(float& c0, float& c1, float& c2, float& c3,
                                         uint32_t a0, uint32_t a1, uint32_t a2, uint32_t a3,
                                         uint32_t b0, uint32_t b1) {
    asm volatile(
        "mma.sync.aligned.m16n8k8.row.col.f32.tf32.tf32.f32 "
        "{%0,%1,%2,%3}, {%4,%5,%6,%7}, {%8,%9}, {%0,%1,%2,%3};\n"
        : "+f"(c0), "+f"(c1), "+f"(c2), "+f"(c3)
        : "r"(a0), "r"(a1), "r"(a2), "r"(a3), "r"(b0), "r"(b1));
}

// Computes the 128x128 block tile accumulators for this thread.
// acc layout: acc[msub][nsub][4]  (msub 0..1, nsub 0..7)
__device__ __forceinline__ void gemm_tile_tf32(
    const float* __restrict__ A, const float* __restrict__ W,
    int K, int blockRow, int blockCol, int mRows,
    float acc[2][8][4])
{
    __shared__ uint32_t As[128 * SMSTRIDE];
    __shared__ uint32_t Bs[128 * SMSTRIDE];

    const int tid  = threadIdx.x;
    const int warp = tid >> 5;
    const int lane = tid & 31;
    const int warp_m = warp >> 1;   // 0..3  -> rows warp_m*32
    const int warp_n = warp & 1;    // 0..1  -> cols warp_n*64
    const int grp  = lane >> 2;     // 0..7
    const int thr  = lane & 3;      // 0..3

    #pragma unroll
    for (int i = 0; i < 2; i++)
        #pragma unroll
        for (int j = 0; j < 8; j++)
            #pragma unroll
            for (int c = 0; c < 4; c++) acc[i][j][c] = 0.f;

    for (int k0 = 0; k0 < K; k0 += 32) {
        // Stage A tile [128 x 32]
        #pragma unroll
        for (int it = 0; it < 4; it++) {
            int idx = it * 256 + tid;
            int r   = idx >> 3;
            int c4  = (idx & 7) * 4;
            int gr  = blockRow * 128 + r;
            float4 v = (gr < mRows)
                ? *reinterpret_cast<const float4*>(A + (size_t)gr * K + k0 + c4)
                : make_float4(0.f, 0.f, 0.f, 0.f);
            uint32_t* p = &As[r * SMSTRIDE + c4];
            p[0] = to_tf32(v.x); p[1] = to_tf32(v.y);
            p[2] = to_tf32(v.z); p[3] = to_tf32(v.w);
        }
        // Stage B tile [128 x 32] (W rows = output cols; always in range)
        #pragma unroll
        for (int it = 0; it < 4; it++) {
            int idx = it * 256 + tid;
            int r   = idx >> 3;
            int c4  = (idx & 7) * 4;
            int gr  = blockCol * 128 + r;
            float4 v = *reinterpret_cast<const float4*>(W + (size_t)gr * K + k0 + c4);
            uint32_t* p = &Bs[r * SMSTRIDE + c4];
            p[0] = to_tf32(v.x); p[1] = to_tf32(v.y);
            p[2] = to_tf32(v.z); p[3] = to_tf32(v.w);
        }
        __syncthreads();

        #pragma unroll
        for (int kk = 0; kk < 32; kk += 8) {
            // A fragments for 2 m-subtiles
            uint32_t af[2][4];
            #pragma unroll
            for (int ms = 0; ms < 2; ms++) {
                int rbase = warp_m * 32 + ms * 16;
                const uint32_t* pa0 = &As[(rbase + grp)     * SMSTRIDE + kk + thr];
                const uint32_t* pa1 = &As[(rbase + grp + 8) * SMSTRIDE + kk + thr];
                af[ms][0] = pa0[0];
                af[ms][1] = pa1[0];
                af[ms][2] = pa0[4];
                af[ms][3] = pa1[4];
            }
            // B fragments for 8 n-subtiles
            uint32_t bf[8][2];
            #pragma unroll
            for (int ns = 0; ns < 8; ns++) {
                int nrow = warp_n * 64 + ns * 8 + grp;
                const uint32_t* pb = &Bs[nrow * SMSTRIDE + kk + thr];
                bf[ns][0] = pb[0];
                bf[ns][1] = pb[4];
            }
            #pragma unroll
            for (int ms = 0; ms < 2; ms++)
                #pragma unroll
                for (int ns = 0; ns < 8; ns++)
                    mma_tf32(acc[ms][ns][0], acc[ms][ns][1], acc[ms][ns][2], acc[ms][ns][3],
                             af[ms][0], af[ms][1], af[ms][2], af[ms][3],
                             bf[ns][0], bf[ns][1]);
        }
        __syncthreads();
    }
}

__global__ __launch_bounds__(256) void qkv_kernel(
    const float* __restrict__ x,      // [MROWS, DIM]
    const float* __restrict__ w,      // [QKV_COLS, DIM]
    const float* __restrict__ bias)   // [QKV_COLS]
{
    float acc[2][8][4];
    gemm_tile_tf32(x, w, DIM, blockIdx.x, blockIdx.y, MROWS, acc);

    const int tid  = threadIdx.x;
    const int warp = tid >> 5;
    const int lane = tid & 31;
    const int warp_m = warp >> 1;
    const int warp_n = warp & 1;
    const int grp = lane >> 2;
    const int thr = lane & 3;

    #pragma unroll
    for (int ms = 0; ms < 2; ms++) {
        #pragma unroll
        for (int ns = 0; ns < 8; ns++) {
            #pragma unroll
            for (int c = 0; c < 4; c++) {
                int m = blockIdx.x * 128 + warp_m * 32 + ms * 16 + grp + ((c >= 2) ? 8 : 0);
                if (m >= MROWS) continue;
                int e = blockIdx.y * 128 + warp_n * 64 + ns * 8 + thr * 2 + (c & 1);
                float val = acc[ms][ns][c] + __ldg(&bias[e]);
                int b = m / SEQ;
                int n = m - b * SEQ;
                int which = e / DIM;       // 0=q,1=k,2=v
                int d = e - which * DIM;
                int h = d >> 6;
                int hh = d & 63;
                float* dst = (which == 0) ? g_q : (which == 1) ? g_k : g_v;
                dst[(((size_t)b * NH + h) * SEQ + n) * HD + hh] = val;
            }
        }
    }
}

__global__ __launch_bounds__(256) void proj_kernel(
    const float* __restrict__ w,      // [DIM, DIM]
    const float* __restrict__ bias,   // [DIM]
    float* __restrict__ out)          // [MROWS, DIM]
{
    float acc[2][8][4];
    gemm_tile_tf32(g_ao, w, DIM, blockIdx.x, blockIdx.y, MROWS, acc);

    const int tid  = threadIdx.x;
    const int warp = tid >> 5;
    const int lane = tid & 31;
    const int warp_m = warp >> 1;
    const int warp_n = warp & 1;
    const int grp = lane >> 2;
    const int thr = lane & 3;

    #pragma unroll
    for (int ms = 0; ms < 2; ms++) {
        #pragma unroll
        for (int ns = 0; ns < 8; ns++) {
            #pragma unroll
            for (int c = 0; c < 4; c++) {
                int m = blockIdx.x * 128 + warp_m * 32 + ms * 16 + grp + ((c >= 2) ? 8 : 0);
                if (m >= MROWS) continue;
                int e = blockIdx.y * 128 + warp_n * 64 + ns * 8 + thr * 2 + (c & 1);
                out[(size_t)m * DIM + e] = acc[ms][ns][c] + __ldg(&bias[e]);
            }
        }
    }
}

// ---------------------------------------------------------------------------
// Attention: one block per (b,h). Full K,V in shared. Thread per query row,
// online softmax over the allowed prefix (scale-causal mask => prefix mask).
// ---------------------------------------------------------------------------

__device__ __forceinline__ int kmax_for_row(int r) {
    if (r == 0)  return SEQ;
    if (r < 5)   return 5;
    if (r < 21)  return 21;
    if (r < 85)  return 85;
    return SEQ;
}

__global__ __launch_bounds__(256) void attn_kernel() {
    extern __shared__ float sh[];
    float* Ks = sh;
    float* Vs = sh + SEQ * HD;

    const int bh = blockIdx.x;
    const size_t base = (size_t)bh * SEQ * HD;
    const int tid = threadIdx.x;

    {
        const float4* k4 = reinterpret_cast<const float4*>(g_k + base);
        const float4* v4 = reinterpret_cast<const float4*>(g_v + base);
        float4* ks4 = reinterpret_cast<float4*>(Ks);
        float4* vs4 = reinterpret_cast<float4*>(Vs);
        for (int i = tid; i < SEQ * HD / 4; i += 256) {
            ks4[i] = k4[i];
            vs4[i] = v4[i];
        }
    }
    __syncthreads();

    const int b = bh / NH;
    const int h = bh - b * NH;

    for (int row = tid; row < SEQ; row += 256) {
        float q[HD];
        {
            const float4* q4 = reinterpret_cast<const float4*>(g_q + base + (size_t)row * HD);
            #pragma unroll
            for (int i = 0; i < 16; i++) {
                float4 t = q4[i];
                q[4*i+0] = t.x; q[4*i+1] = t.y; q[4*i+2] = t.z; q[4*i+3] = t.w;
            }
        }

        const int kmax = kmax_for_row(row);
        float mx = -1e30f, l = 0.f;
        float acc[HD];
        #pragma unroll
        for (int d = 0; d < HD; d++) acc[d] = 0.f;

        for (int j = 0; j < kmax; j++) {
            const float* kp = Ks + j * HD;
            float s0 = 0.f, s1 = 0.f, s2 = 0.f, s3 = 0.f;
            #pragma unroll
            for (int d = 0; d < HD; d += 4) {
                s0 = fmaf(q[d+0], kp[d+0], s0);
                s1 = fmaf(q[d+1], kp[d+1], s1);
                s2 = fmaf(q[d+2], kp[d+2], s2);
                s3 = fmaf(q[d+3], kp[d+3], s3);
            }
            float s = ((s0 + s1) + (s2 + s3)) * 0.125f;

            const float* vp = Vs + j * HD;
            if (s <= mx) {
                float p = __expf(s - mx);
                l += p;
                #pragma unroll
                for (int d = 0; d < HD; d++)
                    acc[d] = fmaf(p, vp[d], acc[d]);
            } else {
                float c = __expf(mx - s);
                mx = s;
                l = fmaf(l, c, 1.f);
                #pragma unroll
                for (int d = 0; d < HD; d++)
                    acc[d] = fmaf(acc[d], c, vp[d]);
            }
        }

        const float inv = 1.f / l;
        float* op = g_ao + ((size_t)(b * SEQ + row)) * DIM + h * HD;
        #pragma unroll
        for (int d = 0; d < HD; d++)
            op[d] = acc[d] * inv;
    }
}

// ---------------------------------------------------------------------------

extern "C" void kernel_launch(void* const* d_in, const int* in_sizes, int n_in,
                              void* d_out, int out_size) {
    const float* x      = (const float*)d_in[0];
    const float* qkv_w  = (const float*)d_in[1];
    const float* qkv_b  = (const float*)d_in[2];
    const float* proj_w = (const float*)d_in[3];
    const float* proj_b = (const float*)d_in[4];
    float* out = (float*)d_out;

    const int smem_attn = 2 * SEQ * HD * (int)sizeof(float);  // 174592 B
    cudaFuncSetAttribute(attn_kernel, cudaFuncAttributeMaxDynamicSharedMemorySize, smem_attn);

    dim3 gQkv((MROWS + 127) / 128, QKV_COLS / 128);   // 171 x 18
    qkv_kernel<<<gQkv, 256>>>(x, qkv_w, qkv_b);

    attn_kernel<<<BQ * NH, 256, smem_attn>>>();       // 768 blocks

    dim3 gProj((MROWS + 127) / 128, DIM / 128);       // 171 x 6
    proj_kernel<<<gProj, 256>>>(proj_w, proj_b, out);
}

// round 6
// speedup vs baseline: 3.0067x; 1.5996x over previous
#include <cuda_runtime.h>
#include <cuda_bf16.h>
#include <cstdint>

#define BQ   64
#define SEQ  341
#define DIM  768
#define NH   12
#define HD   64
#define MROWS (BQ * SEQ)      // 21824
#define QKV_COLS (3 * DIM)    // 2304

// Scratch (no device allocation allowed)
__device__ float g_q[(size_t)BQ * NH * SEQ * HD];
__device__ float g_k[(size_t)BQ * NH * SEQ * HD];
__device__ float g_v[(size_t)BQ * NH * SEQ * HD];
__device__ float g_ao[(size_t)MROWS * DIM];

// ---------------------------------------------------------------------------
// TF32 helpers
// ---------------------------------------------------------------------------

__device__ __forceinline__ uint32_t to_tf32(float x) {
    uint32_t y;
    asm("cvt.rna.tf32.f32 %0, %1;" : "=r"(y) : "f"(x));
    return y;
}

__device__ __forceinline__ void mma_tf32(float& c0, float& c1, float& c2, float& c3,
                                         uint32_t a0, uint32_t a1, uint32_t a2, uint32_t a3,
                                         uint32_t b0, uint32_t b1) {
    asm volatile(
        "mma.sync.aligned.m16n8k8.row.col.f32.tf32.tf32.f32 "
        "{%0,%1,%2,%3}, {%4,%5,%6,%7}, {%8,%9}, {%0,%1,%2,%3};\n"
        : "+f"(c0), "+f"(c1), "+f"(c2), "+f"(c3)
        : "r"(a0), "r"(a1), "r"(a2), "r"(a3), "r"(b0), "r"(b1));
}

// ---------------------------------------------------------------------------
// TF32 tensor-core GEMM: C[m,n] = sum_k A[m,k] * W[n,k]
// BM=128, BN=128, BK=32, 256 threads = 8 warps in 4x2 (warp tile 32x64).
// ---------------------------------------------------------------------------

#define SMSTRIDE 36   // 32 + 4 pad

__device__ __forceinline__ void gemm_tile_tf32(
    const float* __restrict__ A, const float* __restrict__ W,
    int K, int blockRow, int blockCol, int mRows,
    float acc[2][8][4])
{
    __shared__ uint32_t As[128 * SMSTRIDE];
    __shared__ uint32_t Bs[128 * SMSTRIDE];

    const int tid  = threadIdx.x;
    const int warp = tid >> 5;
    const int lane = tid & 31;
    const int warp_m = warp >> 1;
    const int warp_n = warp & 1;
    const int grp  = lane >> 2;
    const int thr  = lane & 3;

    #pragma unroll
    for (int i = 0; i < 2; i++)
        #pragma unroll
        for (int j = 0; j < 8; j++)
            #pragma unroll
            for (int c = 0; c < 4; c++) acc[i][j][c] = 0.f;

    for (int k0 = 0; k0 < K; k0 += 32) {
        #pragma unroll
        for (int it = 0; it < 4; it++) {
            int idx = it * 256 + tid;
            int r   = idx >> 3;
            int c4  = (idx & 7) * 4;
            int gr  = blockRow * 128 + r;
            float4 v = (gr < mRows)
                ? *reinterpret_cast<const float4*>(A + (size_t)gr * K + k0 + c4)
                : make_float4(0.f, 0.f, 0.f, 0.f);
            uint32_t* p = &As[r * SMSTRIDE + c4];
            p[0] = to_tf32(v.x); p[1] = to_tf32(v.y);
            p[2] = to_tf32(v.z); p[3] = to_tf32(v.w);
        }
        #pragma unroll
        for (int it = 0; it < 4; it++) {
            int idx = it * 256 + tid;
            int r   = idx >> 3;
            int c4  = (idx & 7) * 4;
            int gr  = blockCol * 128 + r;
            float4 v = *reinterpret_cast<const float4*>(W + (size_t)gr * K + k0 + c4);
            uint32_t* p = &Bs[r * SMSTRIDE + c4];
            p[0] = to_tf32(v.x); p[1] = to_tf32(v.y);
            p[2] = to_tf32(v.z); p[3] = to_tf32(v.w);
        }
        __syncthreads();

        #pragma unroll
        for (int kk = 0; kk < 32; kk += 8) {
            uint32_t af[2][4];
            #pragma unroll
            for (int ms = 0; ms < 2; ms++) {
                int rbase = warp_m * 32 + ms * 16;
                const uint32_t* pa0 = &As[(rbase + grp)     * SMSTRIDE + kk + thr];
                const uint32_t* pa1 = &As[(rbase + grp + 8) * SMSTRIDE + kk + thr];
                af[ms][0] = pa0[0];
                af[ms][1] = pa1[0];
                af[ms][2] = pa0[4];
                af[ms][3] = pa1[4];
            }
            uint32_t bf[8][2];
            #pragma unroll
            for (int ns = 0; ns < 8; ns++) {
                int nrow = warp_n * 64 + ns * 8 + grp;
                const uint32_t* pb = &Bs[nrow * SMSTRIDE + kk + thr];
                bf[ns][0] = pb[0];
                bf[ns][1] = pb[4];
            }
            #pragma unroll
            for (int ms = 0; ms < 2; ms++)
                #pragma unroll
                for (int ns = 0; ns < 8; ns++)
                    mma_tf32(acc[ms][ns][0], acc[ms][ns][1], acc[ms][ns][2], acc[ms][ns][3],
                             af[ms][0], af[ms][1], af[ms][2], af[ms][3],
                             bf[ns][0], bf[ns][1]);
        }
        __syncthreads();
    }
}

__global__ __launch_bounds__(256) void qkv_kernel(
    const float* __restrict__ x,
    const float* __restrict__ w,
    const float* __restrict__ bias)
{
    float acc[2][8][4];
    gemm_tile_tf32(x, w, DIM, blockIdx.x, blockIdx.y, MROWS, acc);

    const int tid  = threadIdx.x;
    const int warp = tid >> 5;
    const int lane = tid & 31;
    const int warp_m = warp >> 1;
    const int warp_n = warp & 1;
    const int grp = lane >> 2;
    const int thr = lane & 3;

    #pragma unroll
    for (int ms = 0; ms < 2; ms++) {
        #pragma unroll
        for (int ns = 0; ns < 8; ns++) {
            #pragma unroll
            for (int c = 0; c < 4; c++) {
                int m = blockIdx.x * 128 + warp_m * 32 + ms * 16 + grp + ((c >= 2) ? 8 : 0);
                if (m >= MROWS) continue;
                int e = blockIdx.y * 128 + warp_n * 64 + ns * 8 + thr * 2 + (c & 1);
                float val = acc[ms][ns][c] + __ldg(&bias[e]);
                int b = m / SEQ;
                int n = m - b * SEQ;
                int which = e / DIM;
                int d = e - which * DIM;
                int h = d >> 6;
                int hh = d & 63;
                float* dst = (which == 0) ? g_q : (which == 1) ? g_k : g_v;
                dst[(((size_t)b * NH + h) * SEQ + n) * HD + hh] = val;
            }
        }
    }
}

__global__ __launch_bounds__(256) void proj_kernel(
    const float* __restrict__ w,
    const float* __restrict__ bias,
    float* __restrict__ out)
{
    float acc[2][8][4];
    gemm_tile_tf32(g_ao, w, DIM, blockIdx.x, blockIdx.y, MROWS, acc);

    const int tid  = threadIdx.x;
    const int warp = tid >> 5;
    const int lane = tid & 31;
    const int warp_m = warp >> 1;
    const int warp_n = warp & 1;
    const int grp = lane >> 2;
    const int thr = lane & 3;

    #pragma unroll
    for (int ms = 0; ms < 2; ms++) {
        #pragma unroll
        for (int ns = 0; ns < 8; ns++) {
            #pragma unroll
            for (int c = 0; c < 4; c++) {
                int m = blockIdx.x * 128 + warp_m * 32 + ms * 16 + grp + ((c >= 2) ? 8 : 0);
                if (m >= MROWS) continue;
                int e = blockIdx.y * 128 + warp_n * 64 + ns * 8 + thr * 2 + (c & 1);
                out[(size_t)m * DIM + e] = acc[ms][ns][c] + __ldg(&bias[e]);
            }
        }
    }
}

// ---------------------------------------------------------------------------
// Tensor-core flash attention over the prefix mask.
// Block = (bh, q-tile of 128). 8 warps; warp w owns q-rows [w*16, w*16+16).
// K iterated in 3 tiles of 128 (padded to 384), online softmax in fp32.
// ---------------------------------------------------------------------------

#define QS 68    // Qs/Ks row stride (64 + 4)
#define PS 132   // Ps/Vts row stride (128 + 4)
#define NEGINF (-1e30f)

__device__ __forceinline__ int kmax_for_row(int r) {
    if (r == 0)  return SEQ;   // CLS attends everywhere
    if (r < 5)   return 5;
    if (r < 21)  return 21;
    if (r < 85)  return 85;
    return SEQ;                // includes padded rows (never written)
}

__global__ __launch_bounds__(256) void attn_mma_kernel() {
    extern __shared__ uint32_t sm[];
    uint32_t* Qs  = sm;                  // [128][QS]
    uint32_t* Ks  = Qs  + 128 * QS;      // [128][QS]
    uint32_t* Vts = Ks  + 128 * QS;      // [64][PS]  (transposed V: [d][key])
    uint32_t* Ps  = Vts + 64 * PS;       // [128][PS]

    const int tid  = threadIdx.x;
    const int warp = tid >> 5;
    const int lane = tid & 31;
    const int grp  = lane >> 2;
    const int thr  = lane & 3;
    const int bh   = blockIdx.x;
    const int qt   = blockIdx.y;
    const size_t base = (size_t)bh * SEQ * HD;
    const int b = bh / NH;
    const int h = bh - b * NH;
    const int w16 = warp * 16;

    // Stage Q tile [128 x 64] as tf32 (zero-fill padded rows)
    for (int idx = tid; idx < 128 * 16; idx += 256) {
        int r  = idx >> 4;
        int c4 = (idx & 15) << 2;
        int qrow = qt * 128 + r;
        float4 v = (qrow < SEQ)
            ? *reinterpret_cast<const float4*>(g_q + base + (size_t)qrow * HD + c4)
            : make_float4(0.f, 0.f, 0.f, 0.f);
        uint32_t* p = &Qs[r * QS + c4];
        p[0] = to_tf32(v.x); p[1] = to_tf32(v.y);
        p[2] = to_tf32(v.z); p[3] = to_tf32(v.w);
    }

    const int gr0 = qt * 128 + w16 + grp;   // this thread's two q-rows
    const int gr1 = gr0 + 8;
    const int km0 = kmax_for_row(gr0);
    const int km1 = kmax_for_row(gr1);

    float m0 = NEGINF, m1 = NEGINF, l0 = 0.f, l1 = 0.f;
    float oacc[8][4];
    #pragma unroll
    for (int no = 0; no < 8; no++)
        #pragma unroll
        for (int c = 0; c < 4; c++) oacc[no][c] = 0.f;

    for (int t = 0; t < 3; t++) {
        __syncthreads();   // Q staged (t=0) / prior tile's MMA reads done (t>0)

        // Stage K tile [128 x 64] and V^T tile [64 x 128] as tf32
        for (int idx = tid; idx < 128 * 16; idx += 256) {
            int r  = idx >> 4;
            int c4 = (idx & 15) << 2;
            int krow = t * 128 + r;
            float4 kv, vv;
            if (krow < SEQ) {
                kv = *reinterpret_cast<const float4*>(g_k + base + (size_t)krow * HD + c4);
                vv = *reinterpret_cast<const float4*>(g_v + base + (size_t)krow * HD + c4);
            } else {
                kv = make_float4(0.f, 0.f, 0.f, 0.f);
                vv = kv;
            }
            uint32_t* p = &Ks[r * QS + c4];
            p[0] = to_tf32(kv.x); p[1] = to_tf32(kv.y);
            p[2] = to_tf32(kv.z); p[3] = to_tf32(kv.w);
            Vts[(c4 + 0) * PS + r] = to_tf32(vv.x);
            Vts[(c4 + 1) * PS + r] = to_tf32(vv.y);
            Vts[(c4 + 2) * PS + r] = to_tf32(vv.z);
            Vts[(c4 + 3) * PS + r] = to_tf32(vv.w);
        }
        __syncthreads();

        // S = Q K^T for this warp's 16 rows x 128 keys
        float sacc[16][4];
        #pragma unroll
        for (int ns = 0; ns < 16; ns++)
            #pragma unroll
            for (int c = 0; c < 4; c++) sacc[ns][c] = 0.f;

        #pragma unroll
        for (int kk = 0; kk < 64; kk += 8) {
            uint32_t a0 = Qs[(w16 + grp)     * QS + kk + thr];
            uint32_t a1 = Qs[(w16 + grp + 8) * QS + kk + thr];
            uint32_t a2 = Qs[(w16 + grp)     * QS + kk + thr + 4];
            uint32_t a3 = Qs[(w16 + grp + 8) * QS + kk + thr + 4];
            #pragma unroll
            for (int ns = 0; ns < 16; ns++) {
                uint32_t b0 = Ks[(ns * 8 + grp) * QS + kk + thr];
                uint32_t b1 = Ks[(ns * 8 + grp) * QS + kk + thr + 4];
                mma_tf32(sacc[ns][0], sacc[ns][1], sacc[ns][2], sacc[ns][3],
                         a0, a1, a2, a3, b0, b1);
            }
        }

        // Scale + prefix mask, tile row max
        float tmax0 = NEGINF, tmax1 = NEGINF;
        #pragma unroll
        for (int ns = 0; ns < 16; ns++) {
            int j0 = t * 128 + ns * 8 + thr * 2;
            sacc[ns][0] = (j0     < km0) ? sacc[ns][0] * 0.125f : NEGINF;
            sacc[ns][1] = (j0 + 1 < km0) ? sacc[ns][1] * 0.125f : NEGINF;
            sacc[ns][2] = (j0     < km1) ? sacc[ns][2] * 0.125f : NEGINF;
            sacc[ns][3] = (j0 + 1 < km1) ? sacc[ns][3] * 0.125f : NEGINF;
            tmax0 = fmaxf(tmax0, fmaxf(sacc[ns][0], sacc[ns][1]));
            tmax1 = fmaxf(tmax1, fmaxf(sacc[ns][2], sacc[ns][3]));
        }
        tmax0 = fmaxf(tmax0, __shfl_xor_sync(0xFFFFFFFFu, tmax0, 1));
        tmax0 = fmaxf(tmax0, __shfl_xor_sync(0xFFFFFFFFu, tmax0, 2));
        tmax1 = fmaxf(tmax1, __shfl_xor_sync(0xFFFFFFFFu, tmax1, 1));
        tmax1 = fmaxf(tmax1, __shfl_xor_sync(0xFFFFFFFFu, tmax1, 2));

        float mn0 = fmaxf(m0, tmax0);
        float mn1 = fmaxf(m1, tmax1);
        float cr0 = __expf(m0 - mn0);   // 0 on first tile (m=-1e30)
        float cr1 = __expf(m1 - mn1);
        m0 = mn0; m1 = mn1;

        float rs0 = 0.f, rs1 = 0.f;
        #pragma unroll
        for (int ns = 0; ns < 16; ns++) {
            sacc[ns][0] = __expf(sacc[ns][0] - mn0);
            sacc[ns][1] = __expf(sacc[ns][1] - mn0);
            sacc[ns][2] = __expf(sacc[ns][2] - mn1);
            sacc[ns][3] = __expf(sacc[ns][3] - mn1);
            rs0 += sacc[ns][0] + sacc[ns][1];
            rs1 += sacc[ns][2] + sacc[ns][3];
        }
        rs0 += __shfl_xor_sync(0xFFFFFFFFu, rs0, 1);
        rs0 += __shfl_xor_sync(0xFFFFFFFFu, rs0, 2);
        rs1 += __shfl_xor_sync(0xFFFFFFFFu, rs1, 1);
        rs1 += __shfl_xor_sync(0xFFFFFFFFu, rs1, 2);
        l0 = l0 * cr0 + rs0;
        l1 = l1 * cr1 + rs1;

        #pragma unroll
        for (int no = 0; no < 8; no++) {
            oacc[no][0] *= cr0; oacc[no][1] *= cr0;
            oacc[no][2] *= cr1; oacc[no][3] *= cr1;
        }

        // Write P tile (tf32)
        #pragma unroll
        for (int ns = 0; ns < 16; ns++) {
            int col = ns * 8 + thr * 2;
            Ps[(w16 + grp)     * PS + col]     = to_tf32(sacc[ns][0]);
            Ps[(w16 + grp)     * PS + col + 1] = to_tf32(sacc[ns][1]);
            Ps[(w16 + grp + 8) * PS + col]     = to_tf32(sacc[ns][2]);
            Ps[(w16 + grp + 8) * PS + col + 1] = to_tf32(sacc[ns][3]);
        }
        __syncthreads();

        // O += P * V   (B operand = V^T[d][key])
        #pragma unroll
        for (int kk = 0; kk < 128; kk += 8) {
            uint32_t a0 = Ps[(w16 + grp)     * PS + kk + thr];
            uint32_t a1 = Ps[(w16 + grp + 8) * PS + kk + thr];
            uint32_t a2 = Ps[(w16 + grp)     * PS + kk + thr + 4];
            uint32_t a3 = Ps[(w16 + grp + 8) * PS + kk + thr + 4];
            #pragma unroll
            for (int no = 0; no < 8; no++) {
                uint32_t b0 = Vts[(no * 8 + grp) * PS + kk + thr];
                uint32_t b1 = Vts[(no * 8 + grp) * PS + kk + thr + 4];
                mma_tf32(oacc[no][0], oacc[no][1], oacc[no][2], oacc[no][3],
                         a0, a1, a2, a3, b0, b1);
            }
        }
    }

    // Normalize and write output rows (skip padded rows)
    float inv0 = 1.f / l0;
    float inv1 = 1.f / l1;
    #pragma unroll
    for (int no = 0; no < 8; no++) {
        int d = no * 8 + thr * 2;
        if (gr0 < SEQ) {
            float* p = g_ao + ((size_t)(b * SEQ + gr0)) * DIM + h * HD + d;
            p[0] = oacc[no][0] * inv0;
            p[1] = oacc[no][1] * inv0;
        }
        if (gr1 < SEQ) {
            float* p = g_ao + ((size_t)(b * SEQ + gr1)) * DIM + h * HD + d;
            p[0] = oacc[no][2] * inv1;
            p[1] = oacc[no][3] * inv1;
        }
    }
}

// ---------------------------------------------------------------------------

extern "C" void kernel_launch(void* const* d_in, const int* in_sizes, int n_in,
                              void* d_out, int out_size) {
    const float* x      = (const float*)d_in[0];
    const float* qkv_w  = (const float*)d_in[1];
    const float* qkv_b  = (const float*)d_in[2];
    const float* proj_w = (const float*)d_in[3];
    const float* proj_b = (const float*)d_in[4];
    float* out = (float*)d_out;

    const int smem_attn = (128 * QS + 128 * QS + 64 * PS + 128 * PS) * (int)sizeof(uint32_t);
    cudaFuncSetAttribute(attn_mma_kernel, cudaFuncAttributeMaxDynamicSharedMemorySize, smem_attn);

    dim3 gQkv((MROWS + 127) / 128, QKV_COLS / 128);   // 171 x 18
    qkv_kernel<<<gQkv, 256>>>(x, qkv_w, qkv_b);

    dim3 gAttn(BQ * NH, 3);                           // 768 x 3
    attn_mma_kernel<<<gAttn, 256, smem_attn>>>();

    dim3 gProj((MROWS + 127) / 128, DIM / 128);       // 171 x 6
    proj_kernel<<<gProj, 256>>>(proj_w, proj_b, out);
}

// round 10
// speedup vs baseline: 3.0971x; 1.0301x over previous
#include <cuda_runtime.h>
#include <cuda_bf16.h>
#include <cstdint>

#define BQ   64
#define SEQ  341
#define DIM  768
#define NH   12
#define HD   64
#define MROWS (BQ * SEQ)      // 21824
#define QKV_COLS (3 * DIM)    // 2304

// Scratch (no device allocation allowed)
__device__ float g_q[(size_t)BQ * NH * SEQ * HD];
__device__ float g_k[(size_t)BQ * NH * SEQ * HD];
__device__ float g_v[(size_t)BQ * NH * SEQ * HD];
__device__ float g_ao[(size_t)MROWS * DIM];

// ---------------------------------------------------------------------------
// TF32 helpers
// ---------------------------------------------------------------------------

__device__ __forceinline__ uint32_t to_tf32(float x) {
    uint32_t y;
    asm("cvt.rna.tf32.f32 %0, %1;" : "=r"(y) : "f"(x));
    return y;
}

__device__ __forceinline__ void mma_tf32(float& c0, float& c1, float& c2, float& c3,
                                         uint32_t a0, uint32_t a1, uint32_t a2, uint32_t a3,
                                         uint32_t b0, uint32_t b1) {
    asm volatile(
        "mma.sync.aligned.m16n8k8.row.col.f32.tf32.tf32.f32 "
        "{%0,%1,%2,%3}, {%4,%5,%6,%7}, {%8,%9}, {%0,%1,%2,%3};\n"
        : "+f"(c0), "+f"(c1), "+f"(c2), "+f"(c3)
        : "r"(a0), "r"(a1), "r"(a2), "r"(a3), "r"(b0), "r"(b1));
}

// ---------------------------------------------------------------------------
// TF32 GEMM, permuted smem layout for LDS.128 fragment loads.
// C[m,n] = sum_k A[m,k]*W[n,k]. BM=BN=128, BK=32, 256 thr, 8 warps 4x2.
// Permutation: element (r, c) (c = local k, 0..31) stored at word
//   r*SMST + (c&3)*8 + (c>>2)
// so thread thr's 8 needed values per row (cols thr+4i) are contiguous.
// ---------------------------------------------------------------------------

#define SMST 36   // words per row (32 + 4; keeps 16B alignment, shifts banks 4/row)

__device__ __forceinline__ void gemm_tile_tf32(
    const float* __restrict__ A, const float* __restrict__ W,
    int K, int blockRow, int blockCol, int mRows,
    float acc[2][8][4])
{
    __shared__ uint32_t As[128 * SMST];
    __shared__ uint32_t Bs[128 * SMST];

    const int tid  = threadIdx.x;
    const int warp = tid >> 5;
    const int lane = tid & 31;
    const int warp_m = warp >> 1;   // 0..3
    const int warp_n = warp & 1;    // 0..1
    const int grp  = lane >> 2;     // 0..7
    const int thr  = lane & 3;      // 0..3

    #pragma unroll
    for (int i = 0; i < 2; i++)
        #pragma unroll
        for (int j = 0; j < 8; j++)
            #pragma unroll
            for (int c = 0; c < 4; c++) acc[i][j][c] = 0.f;

    for (int k0 = 0; k0 < K; k0 += 32) {
        // Stage A and B tiles [128 x 32] as tf32 in permuted layout
        #pragma unroll
        for (int it = 0; it < 4; it++) {
            int idx = it * 256 + tid;
            int r   = idx >> 3;
            int f4  = idx & 7;          // float4 index; cols 4*f4 .. 4*f4+3
            int gr  = blockRow * 128 + r;
            float4 v = (gr < mRows)
                ? *reinterpret_cast<const float4*>(A + (size_t)gr * K + k0 + f4 * 4)
                : make_float4(0.f, 0.f, 0.f, 0.f);
            uint32_t* p = &As[r * SMST + f4];
            p[0]  = to_tf32(v.x);   // c&3 = 0
            p[8]  = to_tf32(v.y);   // c&3 = 1
            p[16] = to_tf32(v.z);
            p[24] = to_tf32(v.w);
        }
        #pragma unroll
        for (int it = 0; it < 4; it++) {
            int idx = it * 256 + tid;
            int r   = idx >> 3;
            int f4  = idx & 7;
            int gc  = blockCol * 128 + r;
            float4 v = *reinterpret_cast<const float4*>(W + (size_t)gc * K + k0 + f4 * 4);
            uint32_t* p = &Bs[r * SMST + f4];
            p[0]  = to_tf32(v.x);
            p[8]  = to_tf32(v.y);
            p[16] = to_tf32(v.z);
            p[24] = to_tf32(v.w);
        }
        __syncthreads();

        // Each uint4 at word (row*SMST + thr*8 + half*4) holds, for this thread:
        //   .x = a-val for k-step 2*half (low), .y = k-step 2*half (high, +4)
        //   .z = k-step 2*half+1 (low),  .w = k-step 2*half+1 (high)
        #pragma unroll
        for (int half = 0; half < 2; half++) {
            uint4 va[2][2];
            #pragma unroll
            for (int ms = 0; ms < 2; ms++) {
                int r0 = warp_m * 32 + ms * 16 + grp;
                va[ms][0] = *reinterpret_cast<const uint4*>(&As[r0 * SMST + thr * 8 + half * 4]);
                va[ms][1] = *reinterpret_cast<const uint4*>(&As[(r0 + 8) * SMST + thr * 8 + half * 4]);
            }
            #pragma unroll
            for (int ns = 0; ns < 8; ns++) {
                int rn = warp_n * 64 + ns * 8 + grp;
                uint4 vb = *reinterpret_cast<const uint4*>(&Bs[rn * SMST + thr * 8 + half * 4]);
                #pragma unroll
                for (int ms = 0; ms < 2; ms++) {
                    mma_tf32(acc[ms][ns][0], acc[ms][ns][1], acc[ms][ns][2], acc[ms][ns][3],
                             va[ms][0].x, va[ms][1].x, va[ms][0].y, va[ms][1].y,
                             vb.x, vb.y);
                    mma_tf32(acc[ms][ns][0], acc[ms][ns][1], acc[ms][ns][2], acc[ms][ns][3],
                             va[ms][0].z, va[ms][1].z, va[ms][0].w, va[ms][1].w,
                             vb.z, vb.w);
                }
            }
        }
        __syncthreads();
    }
}

__global__ __launch_bounds__(256) void qkv_kernel(
    const float* __restrict__ x,      // [MROWS, DIM]
    const float* __restrict__ w,      // [QKV_COLS, DIM]
    const float* __restrict__ bias)   // [QKV_COLS]
{
    const int colT = blockIdx.x;   // fast → A row-tile L2 reuse
    const int rowT = blockIdx.y;
    float acc[2][8][4];
    gemm_tile_tf32(x, w, DIM, rowT, colT, MROWS, acc);

    const int tid  = threadIdx.x;
    const int warp = tid >> 5;
    const int lane = tid & 31;
    const int warp_m = warp >> 1;
    const int warp_n = warp & 1;
    const int grp = lane >> 2;
    const int thr = lane & 3;

    #pragma unroll
    for (int ms = 0; ms < 2; ms++) {
        #pragma unroll
        for (int ns = 0; ns < 8; ns++) {
            #pragma unroll
            for (int c = 0; c < 4; c++) {
                int m = rowT * 128 + warp_m * 32 + ms * 16 + grp + ((c >= 2) ? 8 : 0);
                if (m >= MROWS) continue;
                int e = colT * 128 + warp_n * 64 + ns * 8 + thr * 2 + (c & 1);
                float val = acc[ms][ns][c] + __ldg(&bias[e]);
                int b = m / SEQ;
                int n = m - b * SEQ;
                int which = e / DIM;
                int d = e - which * DIM;
                int h = d >> 6;
                int hh = d & 63;
                float* dst = (which == 0) ? g_q : (which == 1) ? g_k : g_v;
                dst[(((size_t)b * NH + h) * SEQ + n) * HD + hh] = val;
            }
        }
    }
}

__global__ __launch_bounds__(256) void proj_kernel(
    const float* __restrict__ w,
    const float* __restrict__ bias,
    float* __restrict__ out)
{
    const int colT = blockIdx.x;
    const int rowT = blockIdx.y;
    float acc[2][8][4];
    gemm_tile_tf32(g_ao, w, DIM, rowT, colT, MROWS, acc);

    const int tid  = threadIdx.x;
    const int warp = tid >> 5;
    const int lane = tid & 31;
    const int warp_m = warp >> 1;
    const int warp_n = warp & 1;
    const int grp = lane >> 2;
    const int thr = lane & 3;

    #pragma unroll
    for (int ms = 0; ms < 2; ms++) {
        #pragma unroll
        for (int ns = 0; ns < 8; ns++) {
            #pragma unroll
            for (int c = 0; c < 4; c++) {
                int m = rowT * 128 + warp_m * 32 + ms * 16 + grp + ((c >= 2) ? 8 : 0);
                if (m >= MROWS) continue;
                int e = colT * 128 + warp_n * 64 + ns * 8 + thr * 2 + (c & 1);
                out[(size_t)m * DIM + e] = acc[ms][ns][c] + __ldg(&bias[e]);
            }
        }
    }
}

// ---------------------------------------------------------------------------
// Tensor-core flash attention, K-tile = 64.
// Block = (bh, q-tile of 128), 8 warps (warp w: q-rows w*16..w*16+15).
// smem 104 KB → 2 CTAs/SM. V staged untransposed; PV B-fragments read
// V[key][d] directly (bank-conflict-free). Warps fully masked in a key-tile
// skip its compute.
// ---------------------------------------------------------------------------

#define AS 68    // row stride (64 + 4) for Qs/Ks/Vs/Ps
#define KT 64    // key tile
#define NEGINF (-1e30f)

__device__ __forceinline__ int kmax_for_row(int r) {
    if (r == 0)  return SEQ;   // CLS attends everywhere
    if (r < 5)   return 5;
    if (r < 21)  return 21;
    if (r < 85)  return 85;
    return SEQ;
}

__global__ __launch_bounds__(256) void attn_mma_kernel() {
    extern __shared__ uint32_t sm[];
    uint32_t* Qs = sm;                 // [128][AS]
    uint32_t* Ks = Qs + 128 * AS;      // [64][AS]
    uint32_t* Vs = Ks + KT * AS;       // [64][AS]
    uint32_t* Ps = Vs + KT * AS;       // [128][AS]

    const int tid  = threadIdx.x;
    const int warp = tid >> 5;
    const int lane = tid & 31;
    const int grp  = lane >> 2;
    const int thr  = lane & 3;
    const int bh   = blockIdx.x;
    const int qt   = blockIdx.y;
    const size_t base = (size_t)bh * SEQ * HD;
    const int b = bh / NH;
    const int h = bh - b * NH;
    const int w16 = warp * 16;

    // Stage Q tile [128 x 64] as tf32
    for (int idx = tid; idx < 128 * 16; idx += 256) {
        int r  = idx >> 4;
        int c4 = (idx & 15) << 2;
        int qrow = qt * 128 + r;
        float4 v = (qrow < SEQ)
            ? *reinterpret_cast<const float4*>(g_q + base + (size_t)qrow * HD + c4)
            : make_float4(0.f, 0.f, 0.f, 0.f);
        uint32_t* p = &Qs[r * AS + c4];
        p[0] = to_tf32(v.x); p[1] = to_tf32(v.y);
        p[2] = to_tf32(v.z); p[3] = to_tf32(v.w);
    }

    const int gr0 = qt * 128 + w16 + grp;
    const int gr1 = gr0 + 8;
    const int km0 = kmax_for_row(gr0);
    const int km1 = kmax_for_row(gr1);
    // Warp-level key bound: kmax is monotone for r>=1; row 0 (warp 0 of qt 0)
    // attends everywhere.
    const int wkm = (qt == 0 && warp == 0) ? SEQ : kmax_for_row(qt * 128 + w16 + 15);

    float m0 = NEGINF, m1 = NEGINF, l0 = 0.f, l1 = 0.f;
    float oacc[8][4];
    #pragma unroll
    for (int no = 0; no < 8; no++)
        #pragma unroll
        for (int c = 0; c < 4; c++) oacc[no][c] = 0.f;

    for (int t = 0; t < 6; t++) {
        __syncthreads();   // Q staged (t=0) / prior tile reads done (t>0)

        // Stage K and V tiles [64 x 64] as tf32 (row = key, col = d)
        for (int idx = tid; idx < KT * 16; idx += 256) {
            int r  = idx >> 4;
            int c4 = (idx & 15) << 2;
            int krow = t * KT + r;
            float4 kv, vv;
            if (krow < SEQ) {
                kv = *reinterpret_cast<const float4*>(g_k + base + (size_t)krow * HD + c4);
                vv = *reinterpret_cast<const float4*>(g_v + base + (size_t)krow * HD + c4);
            } else {
                kv = make_float4(0.f, 0.f, 0.f, 0.f);
                vv = kv;
            }
            uint32_t* pk = &Ks[r * AS + c4];
            pk[0] = to_tf32(kv.x); pk[1] = to_tf32(kv.y);
            pk[2] = to_tf32(kv.z); pk[3] = to_tf32(kv.w);
            uint32_t* pv = &Vs[r * AS + c4];
            pv[0] = to_tf32(vv.x); pv[1] = to_tf32(vv.y);
            pv[2] = to_tf32(vv.z); pv[3] = to_tf32(vv.w);
        }
        __syncthreads();

        if (t * KT >= wkm) continue;   // whole warp masked in this tile

        // S = Q K^T : 16 q-rows x 64 keys
        float sacc[8][4];
        #pragma unroll
        for (int ns = 0; ns < 8; ns++)
            #pragma unroll
            for (int c = 0; c < 4; c++) sacc[ns][c] = 0.f;

        #pragma unroll
        for (int kk = 0; kk < 64; kk += 8) {
            uint32_t a0 = Qs[(w16 + grp)     * AS + kk + thr];
            uint32_t a1 = Qs[(w16 + grp + 8) * AS + kk + thr];
            uint32_t a2 = Qs[(w16 + grp)     * AS + kk + thr + 4];
            uint32_t a3 = Qs[(w16 + grp + 8) * AS + kk + thr + 4];
            #pragma unroll
            for (int ns = 0; ns < 8; ns++) {
                uint32_t b0 = Ks[(ns * 8 + grp) * AS + kk + thr];
                uint32_t b1 = Ks[(ns * 8 + grp) * AS + kk + thr + 4];
                mma_tf32(sacc[ns][0], sacc[ns][1], sacc[ns][2], sacc[ns][3],
                         a0, a1, a2, a3, b0, b1);
            }
        }

        // Scale + prefix mask + tile max
        float tmax0 = NEGINF, tmax1 = NEGINF;
        #pragma unroll
        for (int ns = 0; ns < 8; ns++) {
            int j0 = t * KT + ns * 8 + thr * 2;
            sacc[ns][0] = (j0     < km0) ? sacc[ns][0] * 0.125f : NEGINF;
            sacc[ns][1] = (j0 + 1 < km0) ? sacc[ns][1] * 0.125f : NEGINF;
            sacc[ns][2] = (j0     < km1) ? sacc[ns][2] * 0.125f : NEGINF;
            sacc[ns][3] = (j0 + 1 < km1) ? sacc[ns][3] * 0.125f : NEGINF;
            tmax0 = fmaxf(tmax0, fmaxf(sacc[ns][0], sacc[ns][1]));
            tmax1 = fmaxf(tmax1, fmaxf(sacc[ns][2], sacc[ns][3]));
        }
        tmax0 = fmaxf(tmax0, __shfl_xor_sync(0xFFFFFFFFu, tmax0, 1));
        tmax0 = fmaxf(tmax0, __shfl_xor_sync(0xFFFFFFFFu, tmax0, 2));
        tmax1 = fmaxf(tmax1, __shfl_xor_sync(0xFFFFFFFFu, tmax1, 1));
        tmax1 = fmaxf(tmax1, __shfl_xor_sync(0xFFFFFFFFu, tmax1, 2));

        float mn0 = fmaxf(m0, tmax0);
        float mn1 = fmaxf(m1, tmax1);
        float cr0 = __expf(m0 - mn0);
        float cr1 = __expf(m1 - mn1);
        m0 = mn0; m1 = mn1;

        float rs0 = 0.f, rs1 = 0.f;
        #pragma unroll
        for (int ns = 0; ns < 8; ns++) {
            sacc[ns][0] = __expf(sacc[ns][0] - mn0);
            sacc[ns][1] = __expf(sacc[ns][1] - mn0);
            sacc[ns][2] = __expf(sacc[ns][2] - mn1);
            sacc[ns][3] = __expf(sacc[ns][3] - mn1);
            rs0 += sacc[ns][0] + sacc[ns][1];
            rs1 += sacc[ns][2] + sacc[ns][3];
        }
        rs0 += __shfl_xor_sync(0xFFFFFFFFu, rs0, 1);
        rs0 += __shfl_xor_sync(0xFFFFFFFFu, rs0, 2);
        rs1 += __shfl_xor_sync(0xFFFFFFFFu, rs1, 1);
        rs1 += __shfl_xor_sync(0xFFFFFFFFu, rs1, 2);
        l0 = l0 * cr0 + rs0;
        l1 = l1 * cr1 + rs1;

        #pragma unroll
        for (int no = 0; no < 8; no++) {
            oacc[no][0] *= cr0; oacc[no][1] *= cr0;
            oacc[no][2] *= cr1; oacc[no][3] *= cr1;
        }

        // P tile (warp-private rows) as tf32
        #pragma unroll
        for (int ns = 0; ns < 8; ns++) {
            int col = ns * 8 + thr * 2;
            Ps[(w16 + grp)     * AS + col]     = to_tf32(sacc[ns][0]);
            Ps[(w16 + grp)     * AS + col + 1] = to_tf32(sacc[ns][1]);
            Ps[(w16 + grp + 8) * AS + col]     = to_tf32(sacc[ns][2]);
            Ps[(w16 + grp + 8) * AS + col + 1] = to_tf32(sacc[ns][3]);
        }
        __syncwarp();

        // O += P V  (B operand read directly from Vs[key][d], col-major frag)
        #pragma unroll
        for (int kk = 0; kk < 64; kk += 8) {
            uint32_t a0 = Ps[(w16 + grp)     * AS + kk + thr];
            uint32_t a1 = Ps[(w16 + grp + 8) * AS + kk + thr];
            uint32_t a2 = Ps[(w16 + grp)     * AS + kk + thr + 4];
            uint32_t a3 = Ps[(w16 + grp + 8) * AS + kk + thr + 4];
            #pragma unroll
            for (int no = 0; no < 8; no++) {
                uint32_t b0 = Vs[(kk + thr)     * AS + no * 8 + grp];
                uint32_t b1 = Vs[(kk + thr + 4) * AS + no * 8 + grp];
                mma_tf32(oacc[no][0], oacc[no][1], oacc[no][2], oacc[no][3],
                         a0, a1, a2, a3, b0, b1);
            }
        }
    }

    float inv0 = 1.f / l0;
    float inv1 = 1.f / l1;
    #pragma unroll
    for (int no = 0; no < 8; no++) {
        int d = no * 8 + thr * 2;
        if (gr0 < SEQ) {
            float* p = g_ao + ((size_t)(b * SEQ + gr0)) * DIM + h * HD + d;
            p[0] = oacc[no][0] * inv0;
            p[1] = oacc[no][1] * inv0;
        }
        if (gr1 < SEQ) {
            float* p = g_ao + ((size_t)(b * SEQ + gr1)) * DIM + h * HD + d;
            p[0] = oacc[no][2] * inv1;
            p[1] = oacc[no][3] * inv1;
        }
    }
}

// ---------------------------------------------------------------------------

extern "C" void kernel_launch(void* const* d_in, const int* in_sizes, int n_in,
                              void* d_out, int out_size) {
    const float* x      = (const float*)d_in[0];
    const float* qkv_w  = (const float*)d_in[1];
    const float* qkv_b  = (const float*)d_in[2];
    const float* proj_w = (const float*)d_in[3];
    const float* proj_b = (const float*)d_in[4];
    float* out = (float*)d_out;

    const int smem_attn = (128 * AS + KT * AS + KT * AS + 128 * AS) * (int)sizeof(uint32_t);
    cudaFuncSetAttribute(attn_mma_kernel, cudaFuncAttributeMaxDynamicSharedMemorySize, smem_attn);

    dim3 gQkv(QKV_COLS / 128, (MROWS + 127) / 128);   // 18 x 171, colTile fast
    qkv_kernel<<<gQkv, 256>>>(x, qkv_w, qkv_b);

    dim3 gAttn(BQ * NH, 3);                           // 768 x 3
    attn_mma_kernel<<<gAttn, 256, smem_attn>>>();

    dim3 gProj(DIM / 128, (MROWS + 127) / 128);       // 6 x 171
    proj_kernel<<<gProj, 256>>>(proj_w, proj_b, out);
}

// round 12
// speedup vs baseline: 3.1570x; 1.0193x over previous
#include <cuda_runtime.h>
#include <cuda_bf16.h>
#include <cstdint>

#define BQ   64
#define SEQ  341
#define DIM  768
#define NH   12
#define HD   64
#define MROWS (BQ * SEQ)      // 21824
#define QKV_COLS (3 * DIM)    // 2304
#define ROWTILES 171          // ceil(21824/128)
#define KTILES   24           // 768/32

// Scratch (no device allocation allowed). __device__ globals are zero-init.
__device__ float g_q[(size_t)BQ * NH * SEQ * HD];
__device__ float g_k[(size_t)BQ * NH * SEQ * HD];
__device__ float g_v[(size_t)BQ * NH * SEQ * HD];

// Pre-formatted tf32-bit tiled buffers: [tile][kTile][r=128][permuted c=32]
__device__ uint32_t g_xt[(size_t)ROWTILES * KTILES * 4096];
__device__ uint32_t g_aot[(size_t)ROWTILES * KTILES * 4096];
__device__ uint32_t g_wq[(size_t)(QKV_COLS / 128) * KTILES * 4096];
__device__ uint32_t g_wp[(size_t)(DIM / 128) * KTILES * 4096];

// ---------------------------------------------------------------------------
// Helpers
// ---------------------------------------------------------------------------

__device__ __forceinline__ uint32_t to_tf32(float x) {
    uint32_t y;
    asm("cvt.rna.tf32.f32 %0, %1;" : "=r"(y) : "f"(x));
    return y;
}

__device__ __forceinline__ void mma_tf32(float& c0, float& c1, float& c2, float& c3,
                                         uint32_t a0, uint32_t a1, uint32_t a2, uint32_t a3,
                                         uint32_t b0, uint32_t b1) {
    asm volatile(
        "mma.sync.aligned.m16n8k8.row.col.f32.tf32.tf32.f32 "
        "{%0,%1,%2,%3}, {%4,%5,%6,%7}, {%8,%9}, {%0,%1,%2,%3};\n"
        : "+f"(c0), "+f"(c1), "+f"(c2), "+f"(c3)
        : "r"(a0), "r"(a1), "r"(a2), "r"(a3), "r"(b0), "r"(b1));
}

#define CP_ASYNC16(dst32, src) \
    asm volatile("cp.async.cg.shared.global [%0], [%1], 16;\n" :: "r"(dst32), "l"(src))
#define CP_COMMIT()  asm volatile("cp.async.commit_group;\n" ::: "memory")
#define CP_WAIT0()   asm volatile("cp.async.wait_group 0;\n" ::: "memory")

// ---------------------------------------------------------------------------
// Format pass: fp32 row-major [nrows x 768] -> tiled permuted tf32 bits.
// word(tile,kt,r,c) = ((tile*24+kt)*128 + r)*32 + (c&3)*8 + (c>>2)
// One block per row, 192 threads (one float4 each).
// ---------------------------------------------------------------------------

__global__ __launch_bounds__(192) void fmt_kernel(
    const float* __restrict__ src, uint32_t* __restrict__ dst)
{
    const int m = blockIdx.x;
    const int f = threadIdx.x;          // float4 index 0..191
    const float4 v = *reinterpret_cast<const float4*>(src + (size_t)m * DIM + f * 4);
    const int rowTile = m >> 7;
    const int r = m & 127;
    const int kt = f >> 3;              // (4f)/32
    const int f4 = f & 7;               // (c>>2)
    uint32_t* p = dst + ((size_t)(rowTile * KTILES + kt) * 128 + r) * 32 + f4;
    p[0]  = to_tf32(v.x);
    p[8]  = to_tf32(v.y);
    p[16] = to_tf32(v.z);
    p[24] = to_tf32(v.w);
}

// ---------------------------------------------------------------------------
// TF32 GEMM on pre-formatted tiles. C[m,n] = sum_k A[m,k]*W[n,k] (+bias).
// BM=BN=128, BK=32, 256 thr (8 warps 4x2). cp.async double-buffered staging.
// mode 0: scatter to g_q/g_k/g_v.  mode 1: out[m][e] = val.
// blockIdx.x = colTile (fast, A-tile L2 reuse), blockIdx.y = rowTile.
// ---------------------------------------------------------------------------

__global__ __launch_bounds__(256) void gemm_fmt_kernel(
    const uint32_t* __restrict__ At, const uint32_t* __restrict__ Wt,
    const float* __restrict__ bias, float* __restrict__ out, int mode)
{
    extern __shared__ uint32_t sh[];
    uint32_t* sA = sh;           // [2][4096]
    uint32_t* sB = sh + 8192;    // [2][4096]

    const int tid  = threadIdx.x;
    const int warp = tid >> 5;
    const int lane = tid & 31;
    const int warp_m = warp >> 1;   // 0..3
    const int warp_n = warp & 1;    // 0..1
    const int grp  = lane >> 2;     // 0..7
    const int thr  = lane & 3;      // 0..3
    const int colT = blockIdx.x;
    const int rowT = blockIdx.y;

    const uint32_t* gA = At + (size_t)rowT * KTILES * 4096;
    const uint32_t* gB = Wt + (size_t)colT * KTILES * 4096;

    float acc[2][8][4];
    #pragma unroll
    for (int i = 0; i < 2; i++)
        #pragma unroll
        for (int j = 0; j < 8; j++)
            #pragma unroll
            for (int c = 0; c < 4; c++) acc[i][j][c] = 0.f;

    // prefetch kt=0 into buffer 0
    {
        uint32_t dA = (uint32_t)__cvta_generic_to_shared(sA);
        uint32_t dB = (uint32_t)__cvta_generic_to_shared(sB);
        #pragma unroll
        for (int i = 0; i < 4; i++) {
            int off = (i * 256 + tid) * 4;
            CP_ASYNC16(dA + off * 4, gA + off);
            CP_ASYNC16(dB + off * 4, gB + off);
        }
        CP_COMMIT();
    }

    for (int kt = 0; kt < KTILES; kt++) {
        const int cur = kt & 1;
        CP_WAIT0();
        __syncthreads();   // staged data visible to all; prior compute done

        if (kt + 1 < KTILES) {
            const int nxt = cur ^ 1;
            uint32_t dA = (uint32_t)__cvta_generic_to_shared(sA + nxt * 4096);
            uint32_t dB = (uint32_t)__cvta_generic_to_shared(sB + nxt * 4096);
            const uint32_t* srcA = gA + (size_t)(kt + 1) * 4096;
            const uint32_t* srcB = gB + (size_t)(kt + 1) * 4096;
            #pragma unroll
            for (int i = 0; i < 4; i++) {
                int off = (i * 256 + tid) * 4;
                CP_ASYNC16(dA + off * 4, srcA + off);
                CP_ASYNC16(dB + off * 4, srcB + off);
            }
            CP_COMMIT();
        }

        const uint32_t* A0 = sA + cur * 4096;
        const uint32_t* B0 = sB + cur * 4096;

        #pragma unroll
        for (int half = 0; half < 2; half++) {
            uint4 va[2][2];
            #pragma unroll
            for (int ms = 0; ms < 2; ms++) {
                int r0 = warp_m * 32 + ms * 16 + grp;
                va[ms][0] = *reinterpret_cast<const uint4*>(&A0[r0 * 32 + thr * 8 + half * 4]);
                va[ms][1] = *reinterpret_cast<const uint4*>(&A0[(r0 + 8) * 32 + thr * 8 + half * 4]);
            }
            #pragma unroll
            for (int ns = 0; ns < 8; ns++) {
                int rn = warp_n * 64 + ns * 8 + grp;
                uint4 vb = *reinterpret_cast<const uint4*>(&B0[rn * 32 + thr * 8 + half * 4]);
                #pragma unroll
                for (int ms = 0; ms < 2; ms++) {
                    mma_tf32(acc[ms][ns][0], acc[ms][ns][1], acc[ms][ns][2], acc[ms][ns][3],
                             va[ms][0].x, va[ms][1].x, va[ms][0].y, va[ms][1].y,
                             vb.x, vb.y);
                    mma_tf32(acc[ms][ns][0], acc[ms][ns][1], acc[ms][ns][2], acc[ms][ns][3],
                             va[ms][0].z, va[ms][1].z, va[ms][0].w, va[ms][1].w,
                             vb.z, vb.w);
                }
            }
        }
        __syncthreads();   // compute done before next prefetch overwrites
    }

    // Epilogue
    #pragma unroll
    for (int ms = 0; ms < 2; ms++) {
        #pragma unroll
        for (int ns = 0; ns < 8; ns++) {
            #pragma unroll
            for (int c = 0; c < 4; c++) {
                int m = rowT * 128 + warp_m * 32 + ms * 16 + grp + ((c >= 2) ? 8 : 0);
                if (m >= MROWS) continue;
                int e = colT * 128 + warp_n * 64 + ns * 8 + thr * 2 + (c & 1);
                float val = acc[ms][ns][c] + __ldg(&bias[e]);
                if (mode == 0) {
                    int b = m / SEQ;
                    int n = m - b * SEQ;
                    int which = e / DIM;
                    int d = e - which * DIM;
                    int h = d >> 6;
                    int hh = d & 63;
                    float* dst = (which == 0) ? g_q : (which == 1) ? g_k : g_v;
                    dst[(((size_t)b * NH + h) * SEQ + n) * HD + hh] = val;
                } else {
                    out[(size_t)m * DIM + e] = val;
                }
            }
        }
    }
}

// ---------------------------------------------------------------------------
// Tensor-core flash attention (R10 version — validated). Output written
// directly into the tiled/permuted tf32 buffer g_aot for the proj GEMM.
// ---------------------------------------------------------------------------

#define AS 68    // row stride (64 + 4)
#define KT 64    // key tile
#define NEGINF (-1e30f)

__device__ __forceinline__ int kmax_for_row(int r) {
    if (r == 0)  return SEQ;
    if (r < 5)   return 5;
    if (r < 21)  return 21;
    if (r < 85)  return 85;
    return SEQ;
}

__global__ __launch_bounds__(256) void attn_mma_kernel() {
    extern __shared__ uint32_t sm[];
    uint32_t* Qs = sm;                 // [128][AS]
    uint32_t* Ks = Qs + 128 * AS;      // [64][AS]
    uint32_t* Vs = Ks + KT * AS;       // [64][AS]
    uint32_t* Ps = Vs + KT * AS;       // [128][AS]

    const int tid  = threadIdx.x;
    const int warp = tid >> 5;
    const int lane = tid & 31;
    const int grp  = lane >> 2;
    const int thr  = lane & 3;
    const int bh   = blockIdx.x;
    const int qt   = blockIdx.y;
    const size_t base = (size_t)bh * SEQ * HD;
    const int b = bh / NH;
    const int h = bh - b * NH;
    const int w16 = warp * 16;

    for (int idx = tid; idx < 128 * 16; idx += 256) {
        int r  = idx >> 4;
        int c4 = (idx & 15) << 2;
        int qrow = qt * 128 + r;
        float4 v = (qrow < SEQ)
            ? *reinterpret_cast<const float4*>(g_q + base + (size_t)qrow * HD + c4)
            : make_float4(0.f, 0.f, 0.f, 0.f);
        uint32_t* p = &Qs[r * AS + c4];
        p[0] = to_tf32(v.x); p[1] = to_tf32(v.y);
        p[2] = to_tf32(v.z); p[3] = to_tf32(v.w);
    }

    const int gr0 = qt * 128 + w16 + grp;
    const int gr1 = gr0 + 8;
    const int km0 = kmax_for_row(gr0);
    const int km1 = kmax_for_row(gr1);
    const int wkm = (qt == 0 && warp == 0) ? SEQ : kmax_for_row(qt * 128 + w16 + 15);

    float m0 = NEGINF, m1 = NEGINF, l0 = 0.f, l1 = 0.f;
    float oacc[8][4];
    #pragma unroll
    for (int no = 0; no < 8; no++)
        #pragma unroll
        for (int c = 0; c < 4; c++) oacc[no][c] = 0.f;

    for (int t = 0; t < 6; t++) {
        __syncthreads();

        for (int idx = tid; idx < KT * 16; idx += 256) {
            int r  = idx >> 4;
            int c4 = (idx & 15) << 2;
            int krow = t * KT + r;
            float4 kv, vv;
            if (krow < SEQ) {
                kv = *reinterpret_cast<const float4*>(g_k + base + (size_t)krow * HD + c4);
                vv = *reinterpret_cast<const float4*>(g_v + base + (size_t)krow * HD + c4);
            } else {
                kv = make_float4(0.f, 0.f, 0.f, 0.f);
                vv = kv;
            }
            uint32_t* pk = &Ks[r * AS + c4];
            pk[0] = to_tf32(kv.x); pk[1] = to_tf32(kv.y);
            pk[2] = to_tf32(kv.z); pk[3] = to_tf32(kv.w);
            uint32_t* pv = &Vs[r * AS + c4];
            pv[0] = to_tf32(vv.x); pv[1] = to_tf32(vv.y);
            pv[2] = to_tf32(vv.z); pv[3] = to_tf32(vv.w);
        }
        __syncthreads();

        if (t * KT >= wkm) continue;

        float sacc[8][4];
        #pragma unroll
        for (int ns = 0; ns < 8; ns++)
            #pragma unroll
            for (int c = 0; c < 4; c++) sacc[ns][c] = 0.f;

        #pragma unroll
        for (int kk = 0; kk < 64; kk += 8) {
            uint32_t a0 = Qs[(w16 + grp)     * AS + kk + thr];
            uint32_t a1 = Qs[(w16 + grp + 8) * AS + kk + thr];
            uint32_t a2 = Qs[(w16 + grp)     * AS + kk + thr + 4];
            uint32_t a3 = Qs[(w16 + grp + 8) * AS + kk + thr + 4];
            #pragma unroll
            for (int ns = 0; ns < 8; ns++) {
                uint32_t b0 = Ks[(ns * 8 + grp) * AS + kk + thr];
                uint32_t b1 = Ks[(ns * 8 + grp) * AS + kk + thr + 4];
                mma_tf32(sacc[ns][0], sacc[ns][1], sacc[ns][2], sacc[ns][3],
                         a0, a1, a2, a3, b0, b1);
            }
        }

        float tmax0 = NEGINF, tmax1 = NEGINF;
        #pragma unroll
        for (int ns = 0; ns < 8; ns++) {
            int j0 = t * KT + ns * 8 + thr * 2;
            sacc[ns][0] = (j0     < km0) ? sacc[ns][0] * 0.125f : NEGINF;
            sacc[ns][1] = (j0 + 1 < km0) ? sacc[ns][1] * 0.125f : NEGINF;
            sacc[ns][2] = (j0     < km1) ? sacc[ns][2] * 0.125f : NEGINF;
            sacc[ns][3] = (j0 + 1 < km1) ? sacc[ns][3] * 0.125f : NEGINF;
            tmax0 = fmaxf(tmax0, fmaxf(sacc[ns][0], sacc[ns][1]));
            tmax1 = fmaxf(tmax1, fmaxf(sacc[ns][2], sacc[ns][3]));
        }
        tmax0 = fmaxf(tmax0, __shfl_xor_sync(0xFFFFFFFFu, tmax0, 1));
        tmax0 = fmaxf(tmax0, __shfl_xor_sync(0xFFFFFFFFu, tmax0, 2));
        tmax1 = fmaxf(tmax1, __shfl_xor_sync(0xFFFFFFFFu, tmax1, 1));
        tmax1 = fmaxf(tmax1, __shfl_xor_sync(0xFFFFFFFFu, tmax1, 2));

        float mn0 = fmaxf(m0, tmax0);
        float mn1 = fmaxf(m1, tmax1);
        float cr0 = __expf(m0 - mn0);
        float cr1 = __expf(m1 - mn1);
        m0 = mn0; m1 = mn1;

        float rs0 = 0.f, rs1 = 0.f;
        #pragma unroll
        for (int ns = 0; ns < 8; ns++) {
            sacc[ns][0] = __expf(sacc[ns][0] - mn0);
            sacc[ns][1] = __expf(sacc[ns][1] - mn0);
            sacc[ns][2] = __expf(sacc[ns][2] - mn1);
            sacc[ns][3] = __expf(sacc[ns][3] - mn1);
            rs0 += sacc[ns][0] + sacc[ns][1];
            rs1 += sacc[ns][2] + sacc[ns][3];
        }
        rs0 += __shfl_xor_sync(0xFFFFFFFFu, rs0, 1);
        rs0 += __shfl_xor_sync(0xFFFFFFFFu, rs0, 2);
        rs1 += __shfl_xor_sync(0xFFFFFFFFu, rs1, 1);
        rs1 += __shfl_xor_sync(0xFFFFFFFFu, rs1, 2);
        l0 = l0 * cr0 + rs0;
        l1 = l1 * cr1 + rs1;

        #pragma unroll
        for (int no = 0; no < 8; no++) {
            oacc[no][0] *= cr0; oacc[no][1] *= cr0;
            oacc[no][2] *= cr1; oacc[no][3] *= cr1;
        }

        #pragma unroll
        for (int ns = 0; ns < 8; ns++) {
            int col = ns * 8 + thr * 2;
            Ps[(w16 + grp)     * AS + col]     = to_tf32(sacc[ns][0]);
            Ps[(w16 + grp)     * AS + col + 1] = to_tf32(sacc[ns][1]);
            Ps[(w16 + grp + 8) * AS + col]     = to_tf32(sacc[ns][2]);
            Ps[(w16 + grp + 8) * AS + col + 1] = to_tf32(sacc[ns][3]);
        }
        __syncwarp();

        #pragma unroll
        for (int kk = 0; kk < 64; kk += 8) {
            uint32_t a0 = Ps[(w16 + grp)     * AS + kk + thr];
            uint32_t a1 = Ps[(w16 + grp + 8) * AS + kk + thr];
            uint32_t a2 = Ps[(w16 + grp)     * AS + kk + thr + 4];
            uint32_t a3 = Ps[(w16 + grp + 8) * AS + kk + thr + 4];
            #pragma unroll
            for (int no = 0; no < 8; no++) {
                uint32_t b0 = Vs[(kk + thr)     * AS + no * 8 + grp];
                uint32_t b1 = Vs[(kk + thr + 4) * AS + no * 8 + grp];
                mma_tf32(oacc[no][0], oacc[no][1], oacc[no][2], oacc[no][3],
                         a0, a1, a2, a3, b0, b1);
            }
        }
    }

    // Normalize and write DIRECTLY into tiled tf32 buffer g_aot.
    // word(m, e) = ((m>>7)*24 + (e>>5))*4096 + (m&127)*32 + ((e&31)&3)*8 + ((e&31)>>2)
    float inv0 = 1.f / l0;
    float inv1 = 1.f / l1;
    #pragma unroll
    for (int no = 0; no < 8; no++) {
        int d = no * 8 + thr * 2;
        int e = h * HD + d;
        int ktile = e >> 5;
        int c = e & 31;
        uint32_t coff = (uint32_t)((c & 3) * 8 + (c >> 2));
        if (gr0 < SEQ) {
            int mg = b * SEQ + gr0;
            uint32_t* p = g_aot + ((size_t)((mg >> 7) * KTILES + ktile) * 128 + (mg & 127)) * 32 + coff;
            p[0] = to_tf32(oacc[no][0] * inv0);
            p[8] = to_tf32(oacc[no][1] * inv0);
        }
        if (gr1 < SEQ) {
            int mg = b * SEQ + gr1;
            uint32_t* p = g_aot + ((size_t)((mg >> 7) * KTILES + ktile) * 128 + (mg & 127)) * 32 + coff;
            p[0] = to_tf32(oacc[no][2] * inv1);
            p[8] = to_tf32(oacc[no][3] * inv1);
        }
    }
}

// ---------------------------------------------------------------------------

extern "C" void kernel_launch(void* const* d_in, const int* in_sizes, int n_in,
                              void* d_out, int out_size) {
    const float* x      = (const float*)d_in[0];
    const float* qkv_w  = (const float*)d_in[1];
    const float* qkv_b  = (const float*)d_in[2];
    const float* proj_w = (const float*)d_in[3];
    const float* proj_b = (const float*)d_in[4];
    float* out = (float*)d_out;

    uint32_t* xt;  cudaGetSymbolAddress((void**)&xt,  g_xt);
    uint32_t* aot; cudaGetSymbolAddress((void**)&aot, g_aot);
    uint32_t* wq;  cudaGetSymbolAddress((void**)&wq,  g_wq);
    uint32_t* wp;  cudaGetSymbolAddress((void**)&wp,  g_wp);

    const int smem_gemm = 2 * 2 * 4096 * (int)sizeof(uint32_t);  // 65536
    const int smem_attn = (128 * AS + KT * AS + KT * AS + 128 * AS) * (int)sizeof(uint32_t);
    cudaFuncSetAttribute(gemm_fmt_kernel, cudaFuncAttributeMaxDynamicSharedMemorySize, smem_gemm);
    cudaFuncSetAttribute(attn_mma_kernel, cudaFuncAttributeMaxDynamicSharedMemorySize, smem_attn);

    // Format passes
    fmt_kernel<<<MROWS, 192>>>(x, xt);
    fmt_kernel<<<QKV_COLS, 192>>>(qkv_w, wq);
    fmt_kernel<<<DIM, 192>>>(proj_w, wp);

    // QKV GEMM
    dim3 gQkv(QKV_COLS / 128, ROWTILES);   // 18 x 171
    gemm_fmt_kernel<<<gQkv, 256, smem_gemm>>>(xt, wq, qkv_b, nullptr, 0);

    // Attention (writes g_aot tiled)
    dim3 gAttn(BQ * NH, 3);                // 768 x 3
    attn_mma_kernel<<<gAttn, 256, smem_attn>>>();

    // Proj GEMM
    dim3 gProj(DIM / 128, ROWTILES);       // 6 x 171
    gemm_fmt_kernel<<<gProj, 256, smem_gemm>>>(aot, wp, proj_b, out, 1);
}